// round 1
// baseline (speedup 1.0000x reference)
#include <cuda_runtime.h>
#include <cuda_bf16.h>
#include <math.h>

// ---------------- problem constants ----------------
#define BB 4
#define TT 2048
#define EE 1024
#define NHH 16
#define DHH 64
#define NEE 2048
#define HIDD 16
#define MTOK (BB*TT)          // 8192 tokens
#define LN_EPS 1e-5f

// ---------------- scratch (device globals; no runtime allocation) ----------
__device__ float g_h[MTOK * EE];          // LN output (reused LN1/LN2)
__device__ float g_qkv[MTOK * 3 * EE];    // qkv projection
__device__ float g_attn[MTOK * EE];       // attention output (pre-proj)
__device__ float g_logits[MTOK * NEE];    // gate logits
__device__ int   g_idx[MTOK];             // argmax expert per token

// =====================================================================
// LayerNorm: one block per row of 1024, 256 threads, float4 per thread
// =====================================================================
__global__ __launch_bounds__(256) void layernorm_kernel(
    const float* __restrict__ x, const float* __restrict__ gam,
    const float* __restrict__ bet, float* __restrict__ out)
{
    const int row = blockIdx.x;
    const int tid = threadIdx.x;
    const float4 xv = *(const float4*)(x + (size_t)row * EE + tid * 4);

    __shared__ float red[8];

    float s = xv.x + xv.y + xv.z + xv.w;
    #pragma unroll
    for (int o = 16; o; o >>= 1) s += __shfl_xor_sync(0xffffffffu, s, o);
    if ((tid & 31) == 0) red[tid >> 5] = s;
    __syncthreads();
    float tot = 0.f;
    #pragma unroll
    for (int i = 0; i < 8; i++) tot += red[i];
    const float mu = tot * (1.0f / (float)EE);
    __syncthreads();

    const float dx = xv.x - mu, dy = xv.y - mu, dz = xv.z - mu, dw = xv.w - mu;
    float ss = dx*dx + dy*dy + dz*dz + dw*dw;
    #pragma unroll
    for (int o = 16; o; o >>= 1) ss += __shfl_xor_sync(0xffffffffu, ss, o);
    if ((tid & 31) == 0) red[tid >> 5] = ss;
    __syncthreads();
    float sst = 0.f;
    #pragma unroll
    for (int i = 0; i < 8; i++) sst += red[i];
    const float inv = rsqrtf(sst * (1.0f / (float)EE) + LN_EPS);

    const float4 gv = *(const float4*)(gam + tid * 4);
    const float4 bv = *(const float4*)(bet + tid * 4);
    float4 ov;
    ov.x = dx * inv * gv.x + bv.x;
    ov.y = dy * inv * gv.y + bv.y;
    ov.z = dz * inv * gv.z + bv.z;
    ov.w = dw * inv * gv.w + bv.w;
    *(float4*)(out + (size_t)row * EE + tid * 4) = ov;
}

// =====================================================================
// SGEMM: C[M,N] = A[M,K] @ W[K,N] + bias[N] (+ residual)   row-major
// 128x128 block tile, BK=8, 256 threads, 8x8 per thread
// M,N,K multiples of 128/128/8 (true for all calls here)
// =====================================================================
#define GBM 128
#define GBN 128
#define GBK 8
__global__ __launch_bounds__(256) void sgemm_kernel(
    const float* __restrict__ A, const float* __restrict__ W,
    const float* __restrict__ bias, const float* __restrict__ res,
    float* __restrict__ C, int M, int N, int K)
{
    __shared__ float As[GBK][GBM];
    __shared__ float Bs[GBK][GBN];

    const int tid = threadIdx.x;
    const int m0 = blockIdx.y * GBM;
    const int n0 = blockIdx.x * GBN;

    const int aRow = tid >> 1;           // 0..127
    const int aCol = (tid & 1) << 2;     // 0 or 4
    const int bRow = tid >> 5;           // 0..7
    const int bCol = (tid & 31) << 2;    // 0..124

    const int tr = tid >> 4;             // 0..15
    const int tc = tid & 15;             // 0..15

    float acc[8][8];
    #pragma unroll
    for (int i = 0; i < 8; i++)
        #pragma unroll
        for (int j = 0; j < 8; j++) acc[i][j] = 0.f;

    const float* Aptr = A + (size_t)m0 * K;
    const float* Wptr = W + n0;

    for (int k0 = 0; k0 < K; k0 += GBK) {
        float4 av = *(const float4*)(Aptr + (size_t)aRow * K + k0 + aCol);
        As[aCol + 0][aRow] = av.x;
        As[aCol + 1][aRow] = av.y;
        As[aCol + 2][aRow] = av.z;
        As[aCol + 3][aRow] = av.w;
        *(float4*)&Bs[bRow][bCol] =
            *(const float4*)(Wptr + (size_t)(k0 + bRow) * N + bCol);
        __syncthreads();

        #pragma unroll
        for (int k = 0; k < GBK; k++) {
            float ar[8], br[8];
            *(float4*)&ar[0] = *(const float4*)&As[k][tr * 8];
            *(float4*)&ar[4] = *(const float4*)&As[k][tr * 8 + 4];
            *(float4*)&br[0] = *(const float4*)&Bs[k][tc * 8];
            *(float4*)&br[4] = *(const float4*)&Bs[k][tc * 8 + 4];
            #pragma unroll
            for (int i = 0; i < 8; i++)
                #pragma unroll
                for (int j = 0; j < 8; j++)
                    acc[i][j] += ar[i] * br[j];
        }
        __syncthreads();
    }

    #pragma unroll
    for (int i = 0; i < 8; i++) {
        const int m = m0 + tr * 8 + i;
        #pragma unroll
        for (int j = 0; j < 8; j += 4) {
            const int n = n0 + tc * 8 + j;
            float4 v = make_float4(acc[i][j], acc[i][j+1], acc[i][j+2], acc[i][j+3]);
            const float4 bsv = *(const float4*)(bias + n);
            v.x += bsv.x; v.y += bsv.y; v.z += bsv.z; v.w += bsv.w;
            if (res) {
                const float4 rv = *(const float4*)(res + (size_t)m * N + n);
                v.x += rv.x; v.y += rv.y; v.z += rv.z; v.w += rv.w;
            }
            *(float4*)(C + (size_t)m * N + n) = v;
        }
    }
}

// =====================================================================
// Flash attention (causal, fp32). Grid: (T/64, NH, B). 256 thr = 8 warps.
// Warp owns 8 query rows. BN=32 key tile -> full row lives in one warp.
// =====================================================================
__global__ __launch_bounds__(256) void flash_attn_kernel(
    const float* __restrict__ qkv, float* __restrict__ out)
{
    __shared__ float Qs[64][64];
    __shared__ float Kts[64][33];   // transposed K tile, padded
    __shared__ float Vs[32][64];

    const int tid = threadIdx.x;
    const int lane = tid & 31;
    const int warp = tid >> 5;
    const int q0 = blockIdx.x * 64;
    const int h  = blockIdx.y;
    const int b  = blockIdx.z;

    const size_t base = ((size_t)b * TT) * (3 * EE) + (size_t)h * DHH;

    // load Q tile (64 x 64)
    for (int i = tid; i < 64 * 64; i += 256) {
        const int r = i >> 6, d = i & 63;
        Qs[r][d] = qkv[base + (size_t)(q0 + r) * (3 * EE) + d];
    }

    float o0[8], o1[8], m_[8], l_[8];
    #pragma unroll
    for (int r = 0; r < 8; r++) { o0[r]=0.f; o1[r]=0.f; m_[r]=-1e30f; l_[r]=0.f; }

    const int kmax = q0 + 64;
    for (int k0 = 0; k0 < kmax; k0 += 32) {
        __syncthreads();
        for (int i = tid; i < 32 * 64; i += 256) {
            const int c = i >> 6, d = i & 63;
            const size_t g = base + (size_t)(k0 + c) * (3 * EE) + EE + d;
            Kts[d][c] = qkv[g];          // K section
            Vs[c][d]  = qkv[g + EE];     // V section
        }
        __syncthreads();

        // S = Q K^T for this warp's 8 rows; lane owns key column k0+lane
        float s[8];
        #pragma unroll
        for (int r = 0; r < 8; r++) s[r] = 0.f;
        #pragma unroll 8
        for (int d = 0; d < 64; d++) {
            const float kt = Kts[d][lane];
            #pragma unroll
            for (int r = 0; r < 8; r++) s[r] += Qs[warp * 8 + r][d] * kt;
        }

        // online softmax update per row
        const int kj = k0 + lane;
        float p[8];
        #pragma unroll
        for (int r = 0; r < 8; r++) {
            const int qi = q0 + warp * 8 + r;
            float sv = (kj <= qi) ? s[r] * 0.125f : -1e30f;
            float mx = sv;
            #pragma unroll
            for (int o = 16; o; o >>= 1) mx = fmaxf(mx, __shfl_xor_sync(0xffffffffu, mx, o));
            const float mnew = fmaxf(m_[r], mx);
            float pv = __expf(sv - mnew);
            float ps = pv;
            #pragma unroll
            for (int o = 16; o; o >>= 1) ps += __shfl_xor_sync(0xffffffffu, ps, o);
            const float corr = __expf(m_[r] - mnew);
            l_[r] = l_[r] * corr + ps;
            m_[r] = mnew;
            o0[r] *= corr; o1[r] *= corr;
            p[r] = pv;
        }

        // O += P @ V   (c outer so V loads are reused over 8 rows)
        #pragma unroll
        for (int c = 0; c < 32; c++) {
            const float v0 = Vs[c][lane];
            const float v1 = Vs[c][lane + 32];
            #pragma unroll
            for (int r = 0; r < 8; r++) {
                const float pc = __shfl_sync(0xffffffffu, p[r], c);
                o0[r] += pc * v0;
                o1[r] += pc * v1;
            }
        }
    }

    #pragma unroll
    for (int r = 0; r < 8; r++) {
        const int qi = q0 + warp * 8 + r;
        const float inv = 1.0f / l_[r];
        const size_t gb = ((size_t)b * TT + qi) * EE + (size_t)h * DHH;
        out[gb + lane]      = o0[r] * inv;
        out[gb + lane + 32] = o1[r] * inv;
    }
}

// =====================================================================
// Row argmax over 2048 logits (first-occurrence tie-break, like jnp.argmax)
// =====================================================================
__global__ __launch_bounds__(256) void argmax_kernel(
    const float* __restrict__ logits, int* __restrict__ idx)
{
    const int row = blockIdx.x;
    const int tid = threadIdx.x;
    const float* lp = logits + (size_t)row * NEE;
    float best = -3.4e38f; int bi = 0x7fffffff;
    for (int j = tid; j < NEE; j += 256) {
        const float v = lp[j];
        if (v > best) { best = v; bi = j; }
    }
    __shared__ float sv[256];
    __shared__ int   si[256];
    sv[tid] = best; si[tid] = bi;
    __syncthreads();
    for (int s = 128; s > 0; s >>= 1) {
        if (tid < s) {
            if (sv[tid + s] > sv[tid] ||
                (sv[tid + s] == sv[tid] && si[tid + s] < si[tid])) {
                sv[tid] = sv[tid + s]; si[tid] = si[tid + s];
            }
        }
        __syncthreads();
    }
    if (tid == 0) idx[row] = si[0];
}

// =====================================================================
// MoE: one block per token. hmid = gelu(x @ w1[e] + b1[e]);
//      out += hmid @ w2[e] + b2[e]
// =====================================================================
__global__ __launch_bounds__(256) void moe_kernel(
    const float* __restrict__ h, const int* __restrict__ idx,
    const float* __restrict__ w1, const float* __restrict__ b1,
    const float* __restrict__ w2, const float* __restrict__ b2,
    float* __restrict__ out)
{
    const int token = blockIdx.x;
    const int tid = threadIdx.x;
    const int e = idx[token];

    __shared__ float xs[EE];
    __shared__ float partial[HIDD][17];
    __shared__ float hm[HIDD];

    const float* hrow = h + (size_t)token * EE;
    for (int i = tid; i < EE; i += 256) xs[i] = hrow[i];
    __syncthreads();

    const int hcol = tid & 15;
    const int grp  = tid >> 4;  // 0..15
    const float* w1p = w1 + (size_t)e * EE * HIDD;
    float acc = 0.f;
    for (int i = grp; i < EE; i += 16)
        acc += xs[i] * w1p[(size_t)i * HIDD + hcol];
    partial[hcol][grp] = acc;
    __syncthreads();

    if (tid < HIDD) {
        float s = b1[(size_t)e * HIDD + tid];
        #pragma unroll
        for (int g2 = 0; g2 < 16; g2++) s += partial[tid][g2];
        hm[tid] = 0.5f * s * (1.0f + erff(s * 0.70710678118654752f)); // exact gelu
    }
    __syncthreads();

    float hreg[HIDD];
    #pragma unroll
    for (int k = 0; k < HIDD; k++) hreg[k] = hm[k];

    const float* w2p = w2 + (size_t)e * HIDD * EE;
    const float* b2p = b2 + (size_t)e * EE;
    float* orow = out + (size_t)token * EE;
    for (int j = tid; j < EE; j += 256) {
        float s = b2p[j];
        #pragma unroll
        for (int k = 0; k < HIDD; k++) s += hreg[k] * w2p[(size_t)k * EE + j];
        orow[j] += s;
    }
}

// =====================================================================
// launch
// =====================================================================
extern "C" void kernel_launch(void* const* d_in, const int* in_sizes, int n_in,
                              void* d_out, int out_size)
{
    const float* x      = (const float*)d_in[0];
    const float* ln1_g  = (const float*)d_in[1];
    const float* ln1_b  = (const float*)d_in[2];
    const float* ln2_g  = (const float*)d_in[3];
    const float* ln2_b  = (const float*)d_in[4];
    const float* qkv_w  = (const float*)d_in[5];
    const float* qkv_b  = (const float*)d_in[6];
    const float* proj_w = (const float*)d_in[7];
    const float* proj_b = (const float*)d_in[8];
    const float* gate_w = (const float*)d_in[9];
    const float* gate_b = (const float*)d_in[10];
    const float* w1     = (const float*)d_in[11];
    const float* b1     = (const float*)d_in[12];
    const float* w2     = (const float*)d_in[13];
    const float* w2b    = (const float*)d_in[14];
    float* out = (float*)d_out;

    void *p_h, *p_qkv, *p_attn, *p_logits, *p_idx;
    cudaGetSymbolAddress(&p_h, g_h);
    cudaGetSymbolAddress(&p_qkv, g_qkv);
    cudaGetSymbolAddress(&p_attn, g_attn);
    cudaGetSymbolAddress(&p_logits, g_logits);
    cudaGetSymbolAddress(&p_idx, g_idx);
    float* bh      = (float*)p_h;
    float* bqkv    = (float*)p_qkv;
    float* battn   = (float*)p_attn;
    float* blogits = (float*)p_logits;
    int*   bidx    = (int*)p_idx;

    // 1) h = LN1(x)
    layernorm_kernel<<<MTOK, 256>>>(x, ln1_g, ln1_b, bh);

    // 2) qkv = h @ qkv_w + qkv_b
    sgemm_kernel<<<dim3(3*EE/GBN, MTOK/GBM), 256>>>(
        bh, qkv_w, qkv_b, nullptr, bqkv, MTOK, 3*EE, EE);

    // 3) attn = flash_attention(qkv)
    flash_attn_kernel<<<dim3(TT/64, NHH, BB), 256>>>(bqkv, battn);

    // 4) xmid = x + attn @ proj_w + proj_b   -> d_out
    sgemm_kernel<<<dim3(EE/GBN, MTOK/GBM), 256>>>(
        battn, proj_w, proj_b, x, out, MTOK, EE, EE);

    // 5) h = LN2(xmid)
    layernorm_kernel<<<MTOK, 256>>>(out, ln2_g, ln2_b, bh);

    // 6) logits = h @ gate_w + gate_b
    sgemm_kernel<<<dim3(NEE/GBN, MTOK/GBM), 256>>>(
        bh, gate_w, gate_b, nullptr, blogits, MTOK, NEE, EE);

    // 7) idx = argmax(logits)
    argmax_kernel<<<MTOK, 256>>>(blogits, bidx);

    // 8) d_out += moe(h, idx)
    moe_kernel<<<MTOK, 256>>>(bh, bidx, w1, b1, w2, w2b, out);
}

// round 3
// speedup vs baseline: 1.4455x; 1.4455x over previous
#include <cuda_runtime.h>
#include <cuda_bf16.h>
#include <math.h>
#include <stdint.h>

// ---------------- problem constants ----------------
#define BB 4
#define TT 2048
#define EE 1024
#define NHH 16
#define DHH 64
#define NEE 2048
#define HIDD 16
#define MTOK (BB*TT)          // 8192 tokens
#define LN_EPS 1e-5f

// ---------------- scratch (device globals; no runtime allocation) ----------
__device__ float g_h[MTOK * EE];          // LN output (reused LN1/LN2)
__device__ float g_qkv[MTOK * 3 * EE];    // qkv projection
__device__ float g_attn[MTOK * EE];       // attention output (pre-proj)
__device__ float g_logits[MTOK * NEE];    // gate logits
__device__ int   g_idx[MTOK];             // argmax expert per token
// split-bf16 operand buffers
__device__ __nv_bfloat16 g_Ahi[MTOK * EE];          // activations [M,K] row-major
__device__ __nv_bfloat16 g_Alo[MTOK * EE];
__device__ __nv_bfloat16 g_Bhi[3 * EE * EE];        // weights transposed [N,K]
__device__ __nv_bfloat16 g_Blo[3 * EE * EE];

// =====================================================================
// PTX helpers (family-portable: cp.async / ldmatrix / mma.sync only)
// =====================================================================
__device__ __forceinline__ uint32_t smem_u32(const void* p){
    uint32_t a;
    asm("{ .reg .u64 t; cvta.to.shared.u64 t, %1; cvt.u32.u64 %0, t; }"
        : "=r"(a) : "l"(p));
    return a;
}
__device__ __forceinline__ void cp_async16(uint32_t dst, const void* src){
    asm volatile("cp.async.cg.shared.global [%0], [%1], 16;"
        :: "r"(dst), "l"(src));
}
__device__ __forceinline__ void cp_commit(){
    asm volatile("cp.async.commit_group;");
}
template<int N> __device__ __forceinline__ void cp_wait(){
    asm volatile("cp.async.wait_group %0;" :: "n"(N));
}
__device__ __forceinline__ void ldsm_x4(uint32_t* r, uint32_t a){
    asm volatile("ldmatrix.sync.aligned.m8n8.x4.shared.b16 {%0,%1,%2,%3}, [%4];"
        : "=r"(r[0]), "=r"(r[1]), "=r"(r[2]), "=r"(r[3]) : "r"(a));
}
__device__ __forceinline__ void ldsm_x2(uint32_t* r, uint32_t a){
    asm volatile("ldmatrix.sync.aligned.m8n8.x2.shared.b16 {%0,%1}, [%2];"
        : "=r"(r[0]), "=r"(r[1]) : "r"(a));
}
__device__ __forceinline__ void mma16816(float* d, const uint32_t* a, const uint32_t* b){
    asm volatile(
        "mma.sync.aligned.m16n8k16.row.col.f32.bf16.bf16.f32 "
        "{%0,%1,%2,%3}, {%4,%5,%6,%7}, {%8,%9}, {%0,%1,%2,%3};"
        : "+f"(d[0]), "+f"(d[1]), "+f"(d[2]), "+f"(d[3])
        : "r"(a[0]), "r"(a[1]), "r"(a[2]), "r"(a[3]), "r"(b[0]), "r"(b[1]));
}

// =====================================================================
// Conversion: fp32 activations [M,K] -> bf16 hi/lo [M,K] (row-major)
// =====================================================================
__global__ __launch_bounds__(256) void convA_kernel(
    const float* __restrict__ X, __nv_bfloat16* __restrict__ hi,
    __nv_bfloat16* __restrict__ lo)
{
    const size_t i0 = ((size_t)blockIdx.x * 256 + threadIdx.x) * 8;
    float v[8];
    *(float4*)&v[0] = *(const float4*)(X + i0);
    *(float4*)&v[4] = *(const float4*)(X + i0 + 4);
    __nv_bfloat16 h8[8], l8[8];
    #pragma unroll
    for (int t = 0; t < 8; t++) {
        h8[t] = __float2bfloat16(v[t]);
        l8[t] = __float2bfloat16(v[t] - __bfloat162float(h8[t]));
    }
    *(uint4*)(hi + i0) = *(uint4*)h8;
    *(uint4*)(lo + i0) = *(uint4*)l8;
}

// Weights: fp32 W[K,N] -> transposed bf16 hi/lo [N,K]
__global__ __launch_bounds__(256) void convW_kernel(
    const float* __restrict__ W, __nv_bfloat16* __restrict__ hi,
    __nv_bfloat16* __restrict__ lo, int N, int K)
{
    __shared__ float tile[64][65];
    const int k0 = blockIdx.y * 64;
    const int n0 = blockIdx.x * 64;
    for (int i = threadIdx.x; i < 4096; i += 256) {
        const int r = i >> 6, c = i & 63;      // r: k, c: n
        tile[r][c] = W[(size_t)(k0 + r) * N + n0 + c];
    }
    __syncthreads();
    for (int i = threadIdx.x; i < 4096; i += 256) {
        const int r = i >> 6, c = i & 63;      // r: n, c: k
        const float v = tile[c][r];
        const __nv_bfloat16 h = __float2bfloat16(v);
        const __nv_bfloat16 l = __float2bfloat16(v - __bfloat162float(h));
        const size_t o = (size_t)(n0 + r) * K + k0 + c;
        hi[o] = h;
        lo[o] = l;
    }
}

// =====================================================================
// split-bf16 HMMA GEMM: C[M,N] = A[M,K] @ W[K,N] + bias (+ res)
// A hi/lo [M,K], B hi/lo [N,K]. CTA 128x128, BK=32, 2-stage cp.async.
// 256 threads = 8 warps (2 warp_m x 4 warp_n), warp tile 64x32.
// =====================================================================
#define RS 80                      // smem row stride bytes (40 bf16)
#define MATB (128*RS)              // 10240 B per matrix tile
#define STGB (4*MATB)              // 40960 B per stage
#define GEMM_SMEM (512 + 2*STGB)   // bias + 2 stages

__global__ __launch_bounds__(256)
void gemm_tc(const __nv_bfloat16* __restrict__ Ahi, const __nv_bfloat16* __restrict__ Alo,
             const __nv_bfloat16* __restrict__ Bhi, const __nv_bfloat16* __restrict__ Blo,
             const float* __restrict__ bias, const float* __restrict__ res,
             float* __restrict__ C, int N, int K)
{
    extern __shared__ __align__(128) char smem[];
    const int tid = threadIdx.x;
    const int lane = tid & 31, wid = tid >> 5;
    const int warp_m = wid & 1, warp_n = wid >> 1;     // 2 x 4
    const int bn = blockIdx.x, bm = blockIdx.y;
    const uint32_t sb = smem_u32(smem);
    float* bsm = (float*)smem;                          // bias [128]

    if (tid < 128) bsm[tid] = bias[bn * 128 + tid];

    const __nv_bfloat16* gA[2] = { Ahi + (size_t)bm * 128 * K,
                                   Alo + (size_t)bm * 128 * K };
    const __nv_bfloat16* gB[2] = { Bhi + (size_t)bn * 128 * K,
                                   Blo + (size_t)bn * 128 * K };

    // per-thread copy coords: 512 chunks of 16B per matrix, 2 per thread
    const int r0 = tid >> 2, c0 = tid & 3;              // chunk ids tid, tid+256
    const int r1 = (tid + 256) >> 2, c1 = tid & 3;      // (id&3 same)

    auto load_stage = [&](int s, int k0){
        const uint32_t st = sb + 512 + s * STGB;
        #pragma unroll
        for (int m = 0; m < 2; m++) {
            const __nv_bfloat16* src = gA[m] + k0;
            const uint32_t d = st + m * MATB;
            cp_async16(d + r0 * RS + c0 * 16, src + (size_t)r0 * K + c0 * 8);
            cp_async16(d + r1 * RS + c1 * 16, src + (size_t)r1 * K + c1 * 8);
        }
        #pragma unroll
        for (int m = 0; m < 2; m++) {
            const __nv_bfloat16* src = gB[m] + k0;
            const uint32_t d = st + (2 + m) * MATB;
            cp_async16(d + r0 * RS + c0 * 16, src + (size_t)r0 * K + c0 * 8);
            cp_async16(d + r1 * RS + c1 * 16, src + (size_t)r1 * K + c1 * 8);
        }
    };

    float acc[4][4][4];
    #pragma unroll
    for (int i = 0; i < 4; i++)
        #pragma unroll
        for (int j = 0; j < 4; j++)
            #pragma unroll
            for (int t = 0; t < 4; t++) acc[i][j][t] = 0.f;

    const int nk = K >> 5;     // BK=32
    load_stage(0, 0);
    cp_commit();

    const int l15 = lane & 15;
    // A frag smem offsets: rows warp_m*64 + mt*16 + (lane&15), chunk (lane>>4)
    const uint32_t aRowOff = (uint32_t)(warp_m * 64 + l15) * RS + (uint32_t)(lane >> 4) * 16;
    // B frag: rows warp_n*32 + nt*8 + (lane&7), chunk ((lane&15)>>3)
    const uint32_t bRowOff = (uint32_t)(warp_n * 32 + (l15 & 7)) * RS + (uint32_t)(l15 >> 3) * 16;

    for (int c = 0; c < nk; c++) {
        if (c + 1 < nk) { load_stage((c + 1) & 1, (c + 1) * 32); cp_commit(); cp_wait<1>(); }
        else cp_wait<0>();
        __syncthreads();

        const uint32_t st = sb + 512 + (c & 1) * STGB;
        #pragma unroll
        for (int kk = 0; kk < 2; kk++) {
            // B fragments (hi & lo) for 4 n-tiles
            uint32_t bh[4][2], bl[4][2];
            #pragma unroll
            for (int nt = 0; nt < 4; nt++) {
                const uint32_t ba = st + bRowOff + (uint32_t)nt * 8 * RS + kk * 32;
                ldsm_x2(bh[nt], ba + 2 * MATB);
                ldsm_x2(bl[nt], ba + 3 * MATB);
            }
            #pragma unroll
            for (int mt = 0; mt < 4; mt++) {
                const uint32_t aa = st + aRowOff + (uint32_t)mt * 16 * RS + kk * 32;
                uint32_t ah[4], al[4];
                ldsm_x4(ah, aa);
                ldsm_x4(al, aa + MATB);
                #pragma unroll
                for (int nt = 0; nt < 4; nt++) {
                    mma16816(acc[mt][nt], ah, bh[nt]);
                    mma16816(acc[mt][nt], ah, bl[nt]);
                    mma16816(acc[mt][nt], al, bh[nt]);
                }
            }
        }
        __syncthreads();
    }

    // epilogue: d-frag lane map: (row = l>>2 [+8], col = (l&3)*2 {,+1})
    const int mBase = bm * 128 + warp_m * 64;
    const int nBase = warp_n * 32;                 // within block's 128 cols
    const int gn0 = bn * 128;
    #pragma unroll
    for (int mt = 0; mt < 4; mt++) {
        #pragma unroll
        for (int nt = 0; nt < 4; nt++) {
            const int row = mBase + mt * 16 + (lane >> 2);
            const int col = nBase + nt * 8 + (lane & 3) * 2;
            #pragma unroll
            for (int h = 0; h < 2; h++) {          // h=0: rows 0-7, h=1: rows 8-15
                const int m = row + h * 8;
                float2 v;
                v.x = acc[mt][nt][h * 2 + 0] + bsm[col];
                v.y = acc[mt][nt][h * 2 + 1] + bsm[col + 1];
                float* cp = C + (size_t)m * N + gn0 + col;
                if (res) {
                    const float2 rv = *(const float2*)(res + (size_t)m * N + gn0 + col);
                    v.x += rv.x; v.y += rv.y;
                }
                *(float2*)cp = v;
            }
        }
    }
}

// =====================================================================
// LayerNorm: one block per row of 1024, 256 threads, float4 per thread
// =====================================================================
__global__ __launch_bounds__(256) void layernorm_kernel(
    const float* __restrict__ x, const float* __restrict__ gam,
    const float* __restrict__ bet, float* __restrict__ out)
{
    const int row = blockIdx.x;
    const int tid = threadIdx.x;
    const float4 xv = *(const float4*)(x + (size_t)row * EE + tid * 4);

    __shared__ float red[8];

    float s = xv.x + xv.y + xv.z + xv.w;
    #pragma unroll
    for (int o = 16; o; o >>= 1) s += __shfl_xor_sync(0xffffffffu, s, o);
    if ((tid & 31) == 0) red[tid >> 5] = s;
    __syncthreads();
    float tot = 0.f;
    #pragma unroll
    for (int i = 0; i < 8; i++) tot += red[i];
    const float mu = tot * (1.0f / (float)EE);
    __syncthreads();

    const float dx = xv.x - mu, dy = xv.y - mu, dz = xv.z - mu, dw = xv.w - mu;
    float ss = dx*dx + dy*dy + dz*dz + dw*dw;
    #pragma unroll
    for (int o = 16; o; o >>= 1) ss += __shfl_xor_sync(0xffffffffu, ss, o);
    if ((tid & 31) == 0) red[tid >> 5] = ss;
    __syncthreads();
    float sst = 0.f;
    #pragma unroll
    for (int i = 0; i < 8; i++) sst += red[i];
    const float inv = rsqrtf(sst * (1.0f / (float)EE) + LN_EPS);

    const float4 gv = *(const float4*)(gam + tid * 4);
    const float4 bv = *(const float4*)(bet + tid * 4);
    float4 ov;
    ov.x = dx * inv * gv.x + bv.x;
    ov.y = dy * inv * gv.y + bv.y;
    ov.z = dz * inv * gv.z + bv.z;
    ov.w = dw * inv * gv.w + bv.w;
    *(float4*)(out + (size_t)row * EE + tid * 4) = ov;
}

// =====================================================================
// Flash attention (causal, fp32). Grid: (T/64, NH, B). 256 thr = 8 warps.
// =====================================================================
__global__ __launch_bounds__(256) void flash_attn_kernel(
    const float* __restrict__ qkv, float* __restrict__ out)
{
    __shared__ float Qs[64][64];
    __shared__ float Kts[64][33];
    __shared__ float Vs[32][64];

    const int tid = threadIdx.x;
    const int lane = tid & 31;
    const int warp = tid >> 5;
    const int q0 = blockIdx.x * 64;
    const int h  = blockIdx.y;
    const int b  = blockIdx.z;

    const size_t base = ((size_t)b * TT) * (3 * EE) + (size_t)h * DHH;

    for (int i = tid; i < 64 * 64; i += 256) {
        const int r = i >> 6, d = i & 63;
        Qs[r][d] = qkv[base + (size_t)(q0 + r) * (3 * EE) + d];
    }

    float o0[8], o1[8], m_[8], l_[8];
    #pragma unroll
    for (int r = 0; r < 8; r++) { o0[r]=0.f; o1[r]=0.f; m_[r]=-1e30f; l_[r]=0.f; }

    const int kmax = q0 + 64;
    for (int k0 = 0; k0 < kmax; k0 += 32) {
        __syncthreads();
        for (int i = tid; i < 32 * 64; i += 256) {
            const int c = i >> 6, d = i & 63;
            const size_t g = base + (size_t)(k0 + c) * (3 * EE) + EE + d;
            Kts[d][c] = qkv[g];
            Vs[c][d]  = qkv[g + EE];
        }
        __syncthreads();

        float s[8];
        #pragma unroll
        for (int r = 0; r < 8; r++) s[r] = 0.f;
        #pragma unroll 8
        for (int d = 0; d < 64; d++) {
            const float kt = Kts[d][lane];
            #pragma unroll
            for (int r = 0; r < 8; r++) s[r] += Qs[warp * 8 + r][d] * kt;
        }

        const int kj = k0 + lane;
        float p[8];
        #pragma unroll
        for (int r = 0; r < 8; r++) {
            const int qi = q0 + warp * 8 + r;
            float sv = (kj <= qi) ? s[r] * 0.125f : -1e30f;
            float mx = sv;
            #pragma unroll
            for (int o = 16; o; o >>= 1) mx = fmaxf(mx, __shfl_xor_sync(0xffffffffu, mx, o));
            const float mnew = fmaxf(m_[r], mx);
            float pv = __expf(sv - mnew);
            float ps = pv;
            #pragma unroll
            for (int o = 16; o; o >>= 1) ps += __shfl_xor_sync(0xffffffffu, ps, o);
            const float corr = __expf(m_[r] - mnew);
            l_[r] = l_[r] * corr + ps;
            m_[r] = mnew;
            o0[r] *= corr; o1[r] *= corr;
            p[r] = pv;
        }

        #pragma unroll
        for (int c = 0; c < 32; c++) {
            const float v0 = Vs[c][lane];
            const float v1 = Vs[c][lane + 32];
            #pragma unroll
            for (int r = 0; r < 8; r++) {
                const float pc = __shfl_sync(0xffffffffu, p[r], c);
                o0[r] += pc * v0;
                o1[r] += pc * v1;
            }
        }
    }

    #pragma unroll
    for (int r = 0; r < 8; r++) {
        const int qi = q0 + warp * 8 + r;
        const float inv = 1.0f / l_[r];
        const size_t gb = ((size_t)b * TT + qi) * EE + (size_t)h * DHH;
        out[gb + lane]      = o0[r] * inv;
        out[gb + lane + 32] = o1[r] * inv;
    }
}

// =====================================================================
// Row argmax over 2048 logits
// =====================================================================
__global__ __launch_bounds__(256) void argmax_kernel(
    const float* __restrict__ logits, int* __restrict__ idx)
{
    const int row = blockIdx.x;
    const int tid = threadIdx.x;
    const float* lp = logits + (size_t)row * NEE;
    float best = -3.4e38f; int bi = 0x7fffffff;
    for (int j = tid; j < NEE; j += 256) {
        const float v = lp[j];
        if (v > best) { best = v; bi = j; }
    }
    __shared__ float sv[256];
    __shared__ int   si[256];
    sv[tid] = best; si[tid] = bi;
    __syncthreads();
    for (int s = 128; s > 0; s >>= 1) {
        if (tid < s) {
            if (sv[tid + s] > sv[tid] ||
                (sv[tid + s] == sv[tid] && si[tid + s] < si[tid])) {
                sv[tid] = sv[tid + s]; si[tid] = si[tid + s];
            }
        }
        __syncthreads();
    }
    if (tid == 0) idx[row] = si[0];
}

// =====================================================================
// MoE: one block per token
// =====================================================================
__global__ __launch_bounds__(256) void moe_kernel(
    const float* __restrict__ h, const int* __restrict__ idx,
    const float* __restrict__ w1, const float* __restrict__ b1,
    const float* __restrict__ w2, const float* __restrict__ b2,
    float* __restrict__ out)
{
    const int token = blockIdx.x;
    const int tid = threadIdx.x;
    const int e = idx[token];

    __shared__ float xs[EE];
    __shared__ float partial[HIDD][17];
    __shared__ float hm[HIDD];

    const float* hrow = h + (size_t)token * EE;
    for (int i = tid; i < EE; i += 256) xs[i] = hrow[i];
    __syncthreads();

    const int hcol = tid & 15;
    const int grp  = tid >> 4;
    const float* w1p = w1 + (size_t)e * EE * HIDD;
    float acc = 0.f;
    for (int i = grp; i < EE; i += 16)
        acc += xs[i] * w1p[(size_t)i * HIDD + hcol];
    partial[hcol][grp] = acc;
    __syncthreads();

    if (tid < HIDD) {
        float s = b1[(size_t)e * HIDD + tid];
        #pragma unroll
        for (int g2 = 0; g2 < 16; g2++) s += partial[tid][g2];
        hm[tid] = 0.5f * s * (1.0f + erff(s * 0.70710678118654752f));
    }
    __syncthreads();

    float hreg[HIDD];
    #pragma unroll
    for (int k = 0; k < HIDD; k++) hreg[k] = hm[k];

    const float* w2p = w2 + (size_t)e * HIDD * EE;
    const float* b2p = b2 + (size_t)e * EE;
    float* orow = out + (size_t)token * EE;
    for (int j = tid; j < EE; j += 256) {
        float s = b2p[j];
        #pragma unroll
        for (int k = 0; k < HIDD; k++) s += hreg[k] * w2p[(size_t)k * EE + j];
        orow[j] += s;
    }
}

// =====================================================================
// launch
// =====================================================================
extern "C" void kernel_launch(void* const* d_in, const int* in_sizes, int n_in,
                              void* d_out, int out_size)
{
    const float* x      = (const float*)d_in[0];
    const float* ln1_g  = (const float*)d_in[1];
    const float* ln1_b  = (const float*)d_in[2];
    const float* ln2_g  = (const float*)d_in[3];
    const float* ln2_b  = (const float*)d_in[4];
    const float* qkv_w  = (const float*)d_in[5];
    const float* qkv_b  = (const float*)d_in[6];
    const float* proj_w = (const float*)d_in[7];
    const float* proj_b = (const float*)d_in[8];
    const float* gate_w = (const float*)d_in[9];
    const float* gate_b = (const float*)d_in[10];
    const float* w1     = (const float*)d_in[11];
    const float* b1     = (const float*)d_in[12];
    const float* w2     = (const float*)d_in[13];
    const float* w2b    = (const float*)d_in[14];
    float* out = (float*)d_out;

    void *p_h, *p_qkv, *p_attn, *p_logits, *p_idx, *p_ah, *p_al, *p_bh, *p_bl;
    cudaGetSymbolAddress(&p_h, g_h);
    cudaGetSymbolAddress(&p_qkv, g_qkv);
    cudaGetSymbolAddress(&p_attn, g_attn);
    cudaGetSymbolAddress(&p_logits, g_logits);
    cudaGetSymbolAddress(&p_idx, g_idx);
    cudaGetSymbolAddress(&p_ah, g_Ahi);
    cudaGetSymbolAddress(&p_al, g_Alo);
    cudaGetSymbolAddress(&p_bh, g_Bhi);
    cudaGetSymbolAddress(&p_bl, g_Blo);
    float* bh      = (float*)p_h;
    float* bqkv    = (float*)p_qkv;
    float* battn   = (float*)p_attn;
    float* blogits = (float*)p_logits;
    int*   bidx    = (int*)p_idx;
    __nv_bfloat16* Ahi = (__nv_bfloat16*)p_ah;
    __nv_bfloat16* Alo = (__nv_bfloat16*)p_al;
    __nv_bfloat16* Bhi = (__nv_bfloat16*)p_bh;
    __nv_bfloat16* Blo = (__nv_bfloat16*)p_bl;

    cudaFuncSetAttribute(gemm_tc, cudaFuncAttributeMaxDynamicSharedMemorySize, GEMM_SMEM);

    const int convA_blocks = (MTOK * EE) / (256 * 8);

    // 1) h = LN1(x)
    layernorm_kernel<<<MTOK, 256>>>(x, ln1_g, ln1_b, bh);

    // 2) qkv = h @ qkv_w + qkv_b   (split-bf16 HMMA)
    convW_kernel<<<dim3(3*EE/64, EE/64), 256>>>(qkv_w, Bhi, Blo, 3*EE, EE);
    convA_kernel<<<convA_blocks, 256>>>(bh, Ahi, Alo);
    gemm_tc<<<dim3(3*EE/128, MTOK/128), 256, GEMM_SMEM>>>(
        Ahi, Alo, Bhi, Blo, qkv_b, nullptr, bqkv, 3*EE, EE);

    // 3) attn = flash_attention(qkv)
    flash_attn_kernel<<<dim3(TT/64, NHH, BB), 256>>>(bqkv, battn);

    // 4) xmid = x + attn @ proj_w + proj_b   -> d_out
    convW_kernel<<<dim3(EE/64, EE/64), 256>>>(proj_w, Bhi, Blo, EE, EE);
    convA_kernel<<<convA_blocks, 256>>>(battn, Ahi, Alo);
    gemm_tc<<<dim3(EE/128, MTOK/128), 256, GEMM_SMEM>>>(
        Ahi, Alo, Bhi, Blo, proj_b, x, out, EE, EE);

    // 5) h = LN2(xmid)
    layernorm_kernel<<<MTOK, 256>>>(out, ln2_g, ln2_b, bh);

    // 6) logits = h @ gate_w + gate_b
    convW_kernel<<<dim3(NEE/64, EE/64), 256>>>(gate_w, Bhi, Blo, NEE, EE);
    convA_kernel<<<convA_blocks, 256>>>(bh, Ahi, Alo);
    gemm_tc<<<dim3(NEE/128, MTOK/128), 256, GEMM_SMEM>>>(
        Ahi, Alo, Bhi, Blo, gate_b, nullptr, blogits, NEE, EE);

    // 7) idx = argmax(logits)
    argmax_kernel<<<MTOK, 256>>>(blogits, bidx);

    // 8) d_out += moe(h, idx)
    moe_kernel<<<MTOK, 256>>>(bh, bidx, w1, b1, w2, w2b, out);
}

// round 4
// speedup vs baseline: 2.5405x; 1.7576x over previous
#include <cuda_runtime.h>
#include <cuda_bf16.h>
#include <math.h>
#include <stdint.h>

// ---------------- problem constants ----------------
#define BB 4
#define TT 2048
#define EE 1024
#define NHH 16
#define DHH 64
#define NEE 2048
#define HIDD 16
#define MTOK (BB*TT)          // 8192 tokens
#define LN_EPS 1e-5f

// ---------------- scratch (device globals; no runtime allocation) ----------
__device__ float g_h[MTOK * EE];          // LN2 output fp32 (for MoE)
__device__ float g_logits[MTOK * NEE];    // gate logits
__device__ int   g_idx[MTOK];             // argmax expert per token
__device__ __nv_bfloat16 g_Ahi[MTOK * EE];       // GEMM A operand hi [M,K]
__device__ __nv_bfloat16 g_Alo[MTOK * EE];
__device__ __nv_bfloat16 g_Bhi[3 * EE * EE];     // weights transposed [N,K]
__device__ __nv_bfloat16 g_Blo[3 * EE * EE];
__device__ __nv_bfloat16 g_QKVhi[MTOK * 3 * EE]; // qkv bf16 hi/lo
__device__ __nv_bfloat16 g_QKVlo[MTOK * 3 * EE];

// =====================================================================
// PTX helpers (family-portable: cp.async / ldmatrix / mma.sync only)
// =====================================================================
__device__ __forceinline__ uint32_t smem_u32(const void* p){
    uint32_t a;
    asm("{ .reg .u64 t; cvta.to.shared.u64 t, %1; cvt.u32.u64 %0, t; }"
        : "=r"(a) : "l"(p));
    return a;
}
__device__ __forceinline__ void cp_async16(uint32_t dst, const void* src){
    asm volatile("cp.async.cg.shared.global [%0], [%1], 16;"
        :: "r"(dst), "l"(src));
}
__device__ __forceinline__ void cp_commit(){
    asm volatile("cp.async.commit_group;");
}
template<int N> __device__ __forceinline__ void cp_wait(){
    asm volatile("cp.async.wait_group %0;" :: "n"(N));
}
__device__ __forceinline__ void ldsm_x4(uint32_t* r, uint32_t a){
    asm volatile("ldmatrix.sync.aligned.m8n8.x4.shared.b16 {%0,%1,%2,%3}, [%4];"
        : "=r"(r[0]), "=r"(r[1]), "=r"(r[2]), "=r"(r[3]) : "r"(a));
}
__device__ __forceinline__ void ldsm_x4_t(uint32_t* r, uint32_t a){
    asm volatile("ldmatrix.sync.aligned.m8n8.x4.trans.shared.b16 {%0,%1,%2,%3}, [%4];"
        : "=r"(r[0]), "=r"(r[1]), "=r"(r[2]), "=r"(r[3]) : "r"(a));
}
__device__ __forceinline__ void mma16816(float* d, const uint32_t* a, const uint32_t* b){
    asm volatile(
        "mma.sync.aligned.m16n8k16.row.col.f32.bf16.bf16.f32 "
        "{%0,%1,%2,%3}, {%4,%5,%6,%7}, {%8,%9}, {%0,%1,%2,%3};"
        : "+f"(d[0]), "+f"(d[1]), "+f"(d[2]), "+f"(d[3])
        : "r"(a[0]), "r"(a[1]), "r"(a[2]), "r"(a[3]), "r"(b[0]), "r"(b[1]));
}
// split (x,y) into bf16x2 hi (returned) and lo (out param)
__device__ __forceinline__ uint32_t packsplit(float x, float y, uint32_t& lo){
    __nv_bfloat162 h = __floats2bfloat162_rn(x, y);
    __nv_bfloat162 l = __floats2bfloat162_rn(x - __bfloat162float(h.x),
                                             y - __bfloat162float(h.y));
    lo = *(uint32_t*)&l;
    return *(uint32_t*)&h;
}

// =====================================================================
// Weights: fp32 W[K,N] -> transposed bf16 hi/lo [N,K]
// =====================================================================
__global__ __launch_bounds__(256) void convW_kernel(
    const float* __restrict__ W, __nv_bfloat16* __restrict__ hi,
    __nv_bfloat16* __restrict__ lo, int N, int K)
{
    __shared__ float tile[64][65];
    const int k0 = blockIdx.y * 64;
    const int n0 = blockIdx.x * 64;
    for (int i = threadIdx.x; i < 4096; i += 256) {
        const int r = i >> 6, c = i & 63;
        tile[r][c] = W[(size_t)(k0 + r) * N + n0 + c];
    }
    __syncthreads();
    for (int i = threadIdx.x; i < 4096; i += 256) {
        const int r = i >> 6, c = i & 63;
        const float v = tile[c][r];
        const __nv_bfloat16 h = __float2bfloat16(v);
        const __nv_bfloat16 l = __float2bfloat16(v - __bfloat162float(h));
        const size_t o = (size_t)(n0 + r) * K + k0 + c;
        hi[o] = h;
        lo[o] = l;
    }
}

// =====================================================================
// split-bf16 HMMA GEMM: C[M,N] = A[M,K] @ W[K,N] + bias (+ res)
// CTA 128x128, BK=32, 3-stage cp.async, 8 warps (2x4), warp tile 64x32.
// Epilogue: fp32 (Cf) or bf16 hi/lo (outHi/outLo).
// =====================================================================
#define RS 80                      // smem row stride bytes (40 bf16)
#define MATB (128*RS)              // 10240 B per matrix tile
#define STGB (4*MATB)              // 40960 B per stage
#define GEMM_SMEM (512 + 3*STGB)   // bias + 3 stages = 123392

__global__ __launch_bounds__(256)
void gemm_tc(const __nv_bfloat16* __restrict__ Ahi, const __nv_bfloat16* __restrict__ Alo,
             const __nv_bfloat16* __restrict__ Bhi, const __nv_bfloat16* __restrict__ Blo,
             const float* __restrict__ bias, const float* __restrict__ res,
             float* __restrict__ Cf,
             __nv_bfloat16* __restrict__ outHi, __nv_bfloat16* __restrict__ outLo,
             int N, int K)
{
    extern __shared__ __align__(128) char smem[];
    const int tid = threadIdx.x;
    const int lane = tid & 31, wid = tid >> 5;
    const int warp_m = wid & 1, warp_n = wid >> 1;     // 2 x 4
    const int bn = blockIdx.x, bm = blockIdx.y;
    const uint32_t sb = smem_u32(smem);
    float* bsm = (float*)smem;

    if (tid < 128) bsm[tid] = bias[bn * 128 + tid];

    const __nv_bfloat16* gA[2] = { Ahi + (size_t)bm * 128 * K,
                                   Alo + (size_t)bm * 128 * K };
    const __nv_bfloat16* gB[2] = { Bhi + (size_t)bn * 128 * K,
                                   Blo + (size_t)bn * 128 * K };

    const int r0 = tid >> 2, c0 = tid & 3;
    const int r1 = (tid + 256) >> 2;

    auto load_stage = [&](int s, int k0){
        const uint32_t st = sb + 512 + s * STGB;
        #pragma unroll
        for (int m = 0; m < 2; m++) {
            const __nv_bfloat16* src = gA[m] + k0;
            const uint32_t d = st + m * MATB;
            cp_async16(d + r0 * RS + c0 * 16, src + (size_t)r0 * K + c0 * 8);
            cp_async16(d + r1 * RS + c0 * 16, src + (size_t)r1 * K + c0 * 8);
        }
        #pragma unroll
        for (int m = 0; m < 2; m++) {
            const __nv_bfloat16* src = gB[m] + k0;
            const uint32_t d = st + (2 + m) * MATB;
            cp_async16(d + r0 * RS + c0 * 16, src + (size_t)r0 * K + c0 * 8);
            cp_async16(d + r1 * RS + c0 * 16, src + (size_t)r1 * K + c0 * 8);
        }
    };

    float acc[4][4][4];
    #pragma unroll
    for (int i = 0; i < 4; i++)
        #pragma unroll
        for (int j = 0; j < 4; j++)
            #pragma unroll
            for (int t = 0; t < 4; t++) acc[i][j][t] = 0.f;

    const int nk = K >> 5;
    load_stage(0, 0);  cp_commit();
    load_stage(1, 32); cp_commit();

    const int l15 = lane & 15;
    const uint32_t aRowOff = (uint32_t)(warp_m * 64 + l15) * RS + (uint32_t)(lane >> 4) * 16;
    // B x4 loads: rows warp_n*32 + np*16 + (lane&7) + ((lane>>4)<<3), chunk ((lane>>3)&1)
    const uint32_t bRowOff = (uint32_t)(warp_n * 32 + (lane & 7) + ((lane >> 4) << 3)) * RS
                           + (uint32_t)((lane >> 3) & 1) * 16;

    for (int c = 0; c < nk; c++) {
        if (c == nk - 1) cp_wait<0>(); else cp_wait<1>();
        __syncthreads();
        if (c + 2 < nk) { load_stage((c + 2) % 3, (c + 2) * 32); cp_commit(); }

        const uint32_t st = sb + 512 + (c % 3) * STGB;
        #pragma unroll
        for (int kk = 0; kk < 2; kk++) {
            uint32_t bh[2][4], bl[2][4];
            #pragma unroll
            for (int np = 0; np < 2; np++) {
                const uint32_t ba = st + bRowOff + (uint32_t)np * 16 * RS + kk * 32;
                ldsm_x4(bh[np], ba + 2 * MATB);
                ldsm_x4(bl[np], ba + 3 * MATB);
            }
            #pragma unroll
            for (int mt = 0; mt < 4; mt++) {
                const uint32_t aa = st + aRowOff + (uint32_t)mt * 16 * RS + kk * 32;
                uint32_t ah[4], al[4];
                ldsm_x4(ah, aa);
                ldsm_x4(al, aa + MATB);
                #pragma unroll
                for (int nt = 0; nt < 4; nt++) {
                    const uint32_t* ph = &bh[nt >> 1][(nt & 1) * 2];
                    const uint32_t* pl = &bl[nt >> 1][(nt & 1) * 2];
                    mma16816(acc[mt][nt], ah, ph);
                    mma16816(acc[mt][nt], ah, pl);
                    mma16816(acc[mt][nt], al, ph);
                }
            }
        }
    }

    const int mBase = bm * 128 + warp_m * 64;
    const int nBase = warp_n * 32;
    const int gn0 = bn * 128;
    #pragma unroll
    for (int mt = 0; mt < 4; mt++) {
        #pragma unroll
        for (int nt = 0; nt < 4; nt++) {
            const int row = mBase + mt * 16 + (lane >> 2);
            const int col = nBase + nt * 8 + (lane & 3) * 2;
            #pragma unroll
            for (int hh = 0; hh < 2; hh++) {
                const int m = row + hh * 8;
                float vx = acc[mt][nt][hh * 2 + 0] + bsm[col];
                float vy = acc[mt][nt][hh * 2 + 1] + bsm[col + 1];
                if (outHi) {
                    uint32_t lo;
                    const uint32_t hi = packsplit(vx, vy, lo);
                    *(uint32_t*)(outHi + (size_t)m * N + gn0 + col) = hi;
                    *(uint32_t*)(outLo + (size_t)m * N + gn0 + col) = lo;
                } else {
                    if (res) {
                        const float2 rv = *(const float2*)(res + (size_t)m * N + gn0 + col);
                        vx += rv.x; vy += rv.y;
                    }
                    float2 v; v.x = vx; v.y = vy;
                    *(float2*)(Cf + (size_t)m * N + gn0 + col) = v;
                }
            }
        }
    }
}

// =====================================================================
// HMMA flash attention (causal, split-bf16, fp32 softmax)
// Grid (T/128, NH, B), 256 threads = 8 warps, warp owns 16 q rows.
// Q tile 128x64 hi/lo in smem; K/V 64-key tiles, 3-stage cp.async.
// Output written as bf16 hi/lo into GEMM A buffers.
// =====================================================================
#define SRS 144                     // smem row stride (64 bf16 + 16B pad)
#define ATT_MAT (64*SRS)            // 9216
#define ATT_STG (4*ATT_MAT)         // Khi,Klo,Vhi,Vlo = 36864
#define ATT_Q   (128*SRS)           // 18432
#define ATT_SMEM (2*ATT_Q + 3*ATT_STG)   // 147456

__global__ __launch_bounds__(256)
void flash_mma_kernel(const __nv_bfloat16* __restrict__ QKVhi,
                      const __nv_bfloat16* __restrict__ QKVlo,
                      __nv_bfloat16* __restrict__ Ohi,
                      __nv_bfloat16* __restrict__ Olo)
{
    extern __shared__ __align__(128) char smem[];
    const int tid = threadIdx.x, lane = tid & 31, wid = tid >> 5;
    const int qt = (int)gridDim.x - 1 - (int)blockIdx.x;   // heavy blocks first
    const int q0 = qt * 128;
    const int h = blockIdx.y, b = blockIdx.z;

    const uint32_t sQhi = smem_u32(smem);
    const uint32_t sQlo = sQhi + ATT_Q;
    const uint32_t sKV0 = sQlo + ATT_Q;

    const size_t rowStride = 3 * EE;
    const size_t base = ((size_t)b * TT) * rowStride + (size_t)h * DHH;
    const __nv_bfloat16* Qh = QKVhi + base;
    const __nv_bfloat16* Ql = QKVlo + base;
    const __nv_bfloat16* Kh = Qh + EE;
    const __nv_bfloat16* Kl = Ql + EE;
    const __nv_bfloat16* Vh = Qh + 2 * EE;
    const __nv_bfloat16* Vl = Ql + 2 * EE;

    // ---- Q tile load (128 rows x 8 16B chunks, hi+lo) ----
    for (int i = tid; i < 1024; i += 256) {
        const int row = i >> 3, c = i & 7;
        const size_t g = (size_t)(q0 + row) * rowStride + c * 8;
        cp_async16(sQhi + row * SRS + c * 16, Qh + g);
        cp_async16(sQlo + row * SRS + c * 16, Ql + g);
    }

    auto load_kv = [&](int s, int k0){
        const uint32_t st = sKV0 + s * ATT_STG;
        for (int i = tid; i < 512; i += 256) {
            const int row = i >> 3, c = i & 7;
            const size_t g = (size_t)(k0 + row) * rowStride + c * 8;
            const uint32_t d = st + row * SRS + c * 16;
            cp_async16(d + 0 * ATT_MAT, Kh + g);
            cp_async16(d + 1 * ATT_MAT, Kl + g);
            cp_async16(d + 2 * ATT_MAT, Vh + g);
            cp_async16(d + 3 * ATT_MAT, Vl + g);
        }
    };

    const int nk = 2 * qt + 2;      // (q0+128)/64 key tiles
    load_kv(0, 0);  cp_commit();    // group 0 also carries Q
    load_kv(1, 64); cp_commit();

    float acc_o[8][4];
    #pragma unroll
    for (int i = 0; i < 8; i++)
        #pragma unroll
        for (int j = 0; j < 4; j++) acc_o[i][j] = 0.f;
    float m0 = -1e30f, m1 = -1e30f, l0 = 0.f, l1 = 0.f;

    const int l15 = lane & 15;
    const uint32_t qOff = (uint32_t)(wid * 16 + l15) * SRS + (uint32_t)(lane >> 4) * 16;
    const uint32_t kRowOff = (uint32_t)((lane & 7) + ((lane >> 4) << 3)) * SRS
                           + (uint32_t)((lane >> 3) & 1) * 16;
    const uint32_t vRowOff = (uint32_t)((lane & 7) + (((lane >> 3) & 1) << 3)) * SRS
                           + (uint32_t)((lane >> 4) & 1) * 16;

    for (int c = 0; c < nk; c++) {
        if (c == nk - 1) cp_wait<0>(); else cp_wait<1>();
        __syncthreads();
        if (c + 2 < nk) { load_kv((c + 2) % 3, (c + 2) * 64); cp_commit(); }

        const uint32_t Khi_ = sKV0 + (c % 3) * ATT_STG;
        const uint32_t Klo_ = Khi_ + ATT_MAT;
        const uint32_t Vhi_ = Khi_ + 2 * ATT_MAT;
        const uint32_t Vlo_ = Khi_ + 3 * ATT_MAT;
        const int k0 = c * 64;

        // ---- S = Q K^T (split bf16) ----
        float sacc[8][4];
        #pragma unroll
        for (int i = 0; i < 8; i++)
            #pragma unroll
            for (int j = 0; j < 4; j++) sacc[i][j] = 0.f;

        #pragma unroll
        for (int kk = 0; kk < 4; kk++) {
            uint32_t qh[4], ql[4];
            ldsm_x4(qh, sQhi + qOff + kk * 32);
            ldsm_x4(ql, sQlo + qOff + kk * 32);
            #pragma unroll
            for (int np = 0; np < 4; np++) {
                const uint32_t ba = kRowOff + (uint32_t)np * 16 * SRS + kk * 32;
                uint32_t bh[4], bl[4];
                ldsm_x4(bh, Khi_ + ba);
                ldsm_x4(bl, Klo_ + ba);
                #pragma unroll
                for (int t = 0; t < 2; t++) {
                    mma16816(sacc[2 * np + t], qh, &bh[2 * t]);
                    mma16816(sacc[2 * np + t], qh, &bl[2 * t]);
                    mma16816(sacc[2 * np + t], ql, &bh[2 * t]);
                }
            }
        }

        // ---- online softmax (rows r0 = regs {0,1}, r1 = regs {2,3}) ----
        const int rbase = q0 + wid * 16 + (lane >> 2);
        const bool needmask = (k0 + 63) > (q0 + wid * 16);
        #pragma unroll
        for (int nt = 0; nt < 8; nt++) {
            const int col = k0 + nt * 8 + 2 * (lane & 3);
            #pragma unroll
            for (int j = 0; j < 4; j++) {
                float v = sacc[nt][j] * 0.125f;
                if (needmask) {
                    const int cc = col + (j & 1);
                    const int rr = rbase + (j >> 1) * 8;
                    if (cc > rr) v = -1e30f;
                }
                sacc[nt][j] = v;
            }
        }
        float mx0 = -1e30f, mx1 = -1e30f;
        #pragma unroll
        for (int nt = 0; nt < 8; nt++) {
            mx0 = fmaxf(mx0, fmaxf(sacc[nt][0], sacc[nt][1]));
            mx1 = fmaxf(mx1, fmaxf(sacc[nt][2], sacc[nt][3]));
        }
        mx0 = fmaxf(mx0, __shfl_xor_sync(0xffffffffu, mx0, 1));
        mx0 = fmaxf(mx0, __shfl_xor_sync(0xffffffffu, mx0, 2));
        mx1 = fmaxf(mx1, __shfl_xor_sync(0xffffffffu, mx1, 1));
        mx1 = fmaxf(mx1, __shfl_xor_sync(0xffffffffu, mx1, 2));
        const float mn0 = fmaxf(m0, mx0), mn1 = fmaxf(m1, mx1);
        const float cor0 = __expf(m0 - mn0), cor1 = __expf(m1 - mn1);
        float s0 = 0.f, s1 = 0.f;
        #pragma unroll
        for (int nt = 0; nt < 8; nt++) {
            sacc[nt][0] = __expf(sacc[nt][0] - mn0); s0 += sacc[nt][0];
            sacc[nt][1] = __expf(sacc[nt][1] - mn0); s0 += sacc[nt][1];
            sacc[nt][2] = __expf(sacc[nt][2] - mn1); s1 += sacc[nt][2];
            sacc[nt][3] = __expf(sacc[nt][3] - mn1); s1 += sacc[nt][3];
        }
        s0 += __shfl_xor_sync(0xffffffffu, s0, 1);
        s0 += __shfl_xor_sync(0xffffffffu, s0, 2);
        s1 += __shfl_xor_sync(0xffffffffu, s1, 1);
        s1 += __shfl_xor_sync(0xffffffffu, s1, 2);
        l0 = l0 * cor0 + s0; m0 = mn0;
        l1 = l1 * cor1 + s1; m1 = mn1;
        #pragma unroll
        for (int nt = 0; nt < 8; nt++) {
            acc_o[nt][0] *= cor0; acc_o[nt][1] *= cor0;
            acc_o[nt][2] *= cor1; acc_o[nt][3] *= cor1;
        }

        // ---- O += P V (split P, split V) ----
        #pragma unroll
        for (int kkp = 0; kkp < 4; kkp++) {
            uint32_t phi[4], plo[4];
            phi[0] = packsplit(sacc[2*kkp][0],   sacc[2*kkp][1],   plo[0]);
            phi[1] = packsplit(sacc[2*kkp][2],   sacc[2*kkp][3],   plo[1]);
            phi[2] = packsplit(sacc[2*kkp+1][0], sacc[2*kkp+1][1], plo[2]);
            phi[3] = packsplit(sacc[2*kkp+1][2], sacc[2*kkp+1][3], plo[3]);
            #pragma unroll
            for (int np = 0; np < 4; np++) {
                const uint32_t va = (uint32_t)(kkp * 16) * SRS + vRowOff + np * 32;
                uint32_t vh[4], vl[4];
                ldsm_x4_t(vh, Vhi_ + va);
                ldsm_x4_t(vl, Vlo_ + va);
                #pragma unroll
                for (int t = 0; t < 2; t++) {
                    mma16816(acc_o[2 * np + t], phi, &vh[2 * t]);
                    mma16816(acc_o[2 * np + t], phi, &vl[2 * t]);
                    mma16816(acc_o[2 * np + t], plo, &vh[2 * t]);
                }
            }
        }
    }

    // ---- epilogue: O / l, write bf16 hi/lo into GEMM A buffers ----
    const float inv0 = 1.f / l0, inv1 = 1.f / l1;
    const int row0 = b * TT + q0 + wid * 16 + (lane >> 2);
    const int colb = h * DHH + 2 * (lane & 3);
    #pragma unroll
    for (int nt = 0; nt < 8; nt++) {
        const int col = colb + nt * 8;
        uint32_t lo;
        uint32_t hi = packsplit(acc_o[nt][0] * inv0, acc_o[nt][1] * inv0, lo);
        *(uint32_t*)(Ohi + (size_t)row0 * EE + col) = hi;
        *(uint32_t*)(Olo + (size_t)row0 * EE + col) = lo;
        hi = packsplit(acc_o[nt][2] * inv1, acc_o[nt][3] * inv1, lo);
        *(uint32_t*)(Ohi + (size_t)(row0 + 8) * EE + col) = hi;
        *(uint32_t*)(Olo + (size_t)(row0 + 8) * EE + col) = lo;
    }
}

// =====================================================================
// LayerNorm: block per row, 256 threads; optional fp32 + bf16 hi/lo out
// =====================================================================
__global__ __launch_bounds__(256) void layernorm_kernel(
    const float* __restrict__ x, const float* __restrict__ gam,
    const float* __restrict__ bet, float* __restrict__ outF,
    __nv_bfloat16* __restrict__ outHi, __nv_bfloat16* __restrict__ outLo)
{
    const int row = blockIdx.x;
    const int tid = threadIdx.x;
    const float4 xv = *(const float4*)(x + (size_t)row * EE + tid * 4);

    __shared__ float red[8];

    float s = xv.x + xv.y + xv.z + xv.w;
    #pragma unroll
    for (int o = 16; o; o >>= 1) s += __shfl_xor_sync(0xffffffffu, s, o);
    if ((tid & 31) == 0) red[tid >> 5] = s;
    __syncthreads();
    float tot = 0.f;
    #pragma unroll
    for (int i = 0; i < 8; i++) tot += red[i];
    const float mu = tot * (1.0f / (float)EE);
    __syncthreads();

    const float dx = xv.x - mu, dy = xv.y - mu, dz = xv.z - mu, dw = xv.w - mu;
    float ss = dx*dx + dy*dy + dz*dz + dw*dw;
    #pragma unroll
    for (int o = 16; o; o >>= 1) ss += __shfl_xor_sync(0xffffffffu, ss, o);
    if ((tid & 31) == 0) red[tid >> 5] = ss;
    __syncthreads();
    float sst = 0.f;
    #pragma unroll
    for (int i = 0; i < 8; i++) sst += red[i];
    const float inv = rsqrtf(sst * (1.0f / (float)EE) + LN_EPS);

    const float4 gv = *(const float4*)(gam + tid * 4);
    const float4 bv = *(const float4*)(bet + tid * 4);
    float4 ov;
    ov.x = dx * inv * gv.x + bv.x;
    ov.y = dy * inv * gv.y + bv.y;
    ov.z = dz * inv * gv.z + bv.z;
    ov.w = dw * inv * gv.w + bv.w;
    if (outF) *(float4*)(outF + (size_t)row * EE + tid * 4) = ov;
    uint32_t lo0, lo1;
    const uint32_t hi0 = packsplit(ov.x, ov.y, lo0);
    const uint32_t hi1 = packsplit(ov.z, ov.w, lo1);
    uint2 hv; hv.x = hi0; hv.y = hi1;
    uint2 lv; lv.x = lo0; lv.y = lo1;
    *(uint2*)(outHi + (size_t)row * EE + tid * 4) = hv;
    *(uint2*)(outLo + (size_t)row * EE + tid * 4) = lv;
}

// =====================================================================
// Row argmax over 2048 logits
// =====================================================================
__global__ __launch_bounds__(256) void argmax_kernel(
    const float* __restrict__ logits, int* __restrict__ idx)
{
    const int row = blockIdx.x;
    const int tid = threadIdx.x;
    const float* lp = logits + (size_t)row * NEE;
    float best = -3.4e38f; int bi = 0x7fffffff;
    for (int j = tid; j < NEE; j += 256) {
        const float v = lp[j];
        if (v > best) { best = v; bi = j; }
    }
    __shared__ float sv[256];
    __shared__ int   si[256];
    sv[tid] = best; si[tid] = bi;
    __syncthreads();
    for (int s = 128; s > 0; s >>= 1) {
        if (tid < s) {
            if (sv[tid + s] > sv[tid] ||
                (sv[tid + s] == sv[tid] && si[tid + s] < si[tid])) {
                sv[tid] = sv[tid + s]; si[tid] = si[tid + s];
            }
        }
        __syncthreads();
    }
    if (tid == 0) idx[row] = si[0];
}

// =====================================================================
// MoE: one block per token
// =====================================================================
__global__ __launch_bounds__(256) void moe_kernel(
    const float* __restrict__ h, const int* __restrict__ idx,
    const float* __restrict__ w1, const float* __restrict__ b1,
    const float* __restrict__ w2, const float* __restrict__ b2,
    float* __restrict__ out)
{
    const int token = blockIdx.x;
    const int tid = threadIdx.x;
    const int e = idx[token];

    __shared__ float xs[EE];
    __shared__ float partial[HIDD][17];
    __shared__ float hm[HIDD];

    const float* hrow = h + (size_t)token * EE;
    for (int i = tid; i < EE; i += 256) xs[i] = hrow[i];
    __syncthreads();

    const int hcol = tid & 15;
    const int grp  = tid >> 4;
    const float* w1p = w1 + (size_t)e * EE * HIDD;
    float acc = 0.f;
    for (int i = grp; i < EE; i += 16)
        acc += xs[i] * w1p[(size_t)i * HIDD + hcol];
    partial[hcol][grp] = acc;
    __syncthreads();

    if (tid < HIDD) {
        float s = b1[(size_t)e * HIDD + tid];
        #pragma unroll
        for (int g2 = 0; g2 < 16; g2++) s += partial[tid][g2];
        hm[tid] = 0.5f * s * (1.0f + erff(s * 0.70710678118654752f));
    }
    __syncthreads();

    float hreg[HIDD];
    #pragma unroll
    for (int k = 0; k < HIDD; k++) hreg[k] = hm[k];

    const float* w2p = w2 + (size_t)e * HIDD * EE;
    const float* b2p = b2 + (size_t)e * EE;
    float* orow = out + (size_t)token * EE;
    for (int j = tid; j < EE; j += 256) {
        float s = b2p[j];
        #pragma unroll
        for (int k = 0; k < HIDD; k++) s += hreg[k] * w2p[(size_t)k * EE + j];
        orow[j] += s;
    }
}

// =====================================================================
// launch
// =====================================================================
extern "C" void kernel_launch(void* const* d_in, const int* in_sizes, int n_in,
                              void* d_out, int out_size)
{
    const float* x      = (const float*)d_in[0];
    const float* ln1_g  = (const float*)d_in[1];
    const float* ln1_b  = (const float*)d_in[2];
    const float* ln2_g  = (const float*)d_in[3];
    const float* ln2_b  = (const float*)d_in[4];
    const float* qkv_w  = (const float*)d_in[5];
    const float* qkv_b  = (const float*)d_in[6];
    const float* proj_w = (const float*)d_in[7];
    const float* proj_b = (const float*)d_in[8];
    const float* gate_w = (const float*)d_in[9];
    const float* gate_b = (const float*)d_in[10];
    const float* w1     = (const float*)d_in[11];
    const float* b1     = (const float*)d_in[12];
    const float* w2     = (const float*)d_in[13];
    const float* w2b    = (const float*)d_in[14];
    float* out = (float*)d_out;

    void *p_h, *p_logits, *p_idx, *p_ah, *p_al, *p_bh, *p_bl, *p_qh, *p_ql;
    cudaGetSymbolAddress(&p_h, g_h);
    cudaGetSymbolAddress(&p_logits, g_logits);
    cudaGetSymbolAddress(&p_idx, g_idx);
    cudaGetSymbolAddress(&p_ah, g_Ahi);
    cudaGetSymbolAddress(&p_al, g_Alo);
    cudaGetSymbolAddress(&p_bh, g_Bhi);
    cudaGetSymbolAddress(&p_bl, g_Blo);
    cudaGetSymbolAddress(&p_qh, g_QKVhi);
    cudaGetSymbolAddress(&p_ql, g_QKVlo);
    float* bh      = (float*)p_h;
    float* blogits = (float*)p_logits;
    int*   bidx    = (int*)p_idx;
    __nv_bfloat16* Ahi = (__nv_bfloat16*)p_ah;
    __nv_bfloat16* Alo = (__nv_bfloat16*)p_al;
    __nv_bfloat16* Bhi = (__nv_bfloat16*)p_bh;
    __nv_bfloat16* Blo = (__nv_bfloat16*)p_bl;
    __nv_bfloat16* QKVhi = (__nv_bfloat16*)p_qh;
    __nv_bfloat16* QKVlo = (__nv_bfloat16*)p_ql;

    cudaFuncSetAttribute(gemm_tc, cudaFuncAttributeMaxDynamicSharedMemorySize, GEMM_SMEM);
    cudaFuncSetAttribute(flash_mma_kernel, cudaFuncAttributeMaxDynamicSharedMemorySize, ATT_SMEM);

    // 1) LN1(x) -> bf16 hi/lo A operand
    layernorm_kernel<<<MTOK, 256>>>(x, ln1_g, ln1_b, nullptr, Ahi, Alo);

    // 2) qkv = h @ qkv_w + qkv_b -> bf16 hi/lo qkv buffers
    convW_kernel<<<dim3(3*EE/64, EE/64), 256>>>(qkv_w, Bhi, Blo, 3*EE, EE);
    gemm_tc<<<dim3(3*EE/128, MTOK/128), 256, GEMM_SMEM>>>(
        Ahi, Alo, Bhi, Blo, qkv_b, nullptr, nullptr, QKVhi, QKVlo, 3*EE, EE);

    // 3) attention -> bf16 hi/lo into A operand buffers
    flash_mma_kernel<<<dim3(TT/128, NHH, BB), 256, ATT_SMEM>>>(QKVhi, QKVlo, Ahi, Alo);

    // 4) xmid = x + attn @ proj_w + proj_b -> d_out (fp32)
    convW_kernel<<<dim3(EE/64, EE/64), 256>>>(proj_w, Bhi, Blo, EE, EE);
    gemm_tc<<<dim3(EE/128, MTOK/128), 256, GEMM_SMEM>>>(
        Ahi, Alo, Bhi, Blo, proj_b, x, out, nullptr, nullptr, EE, EE);

    // 5) LN2 -> fp32 (MoE) + bf16 hi/lo (gate GEMM)
    layernorm_kernel<<<MTOK, 256>>>(out, ln2_g, ln2_b, bh, Ahi, Alo);

    // 6) logits = h @ gate_w + gate_b (fp32)
    convW_kernel<<<dim3(NEE/64, EE/64), 256>>>(gate_w, Bhi, Blo, NEE, EE);
    gemm_tc<<<dim3(NEE/128, MTOK/128), 256, GEMM_SMEM>>>(
        Ahi, Alo, Bhi, Blo, gate_b, nullptr, blogits, nullptr, nullptr, NEE, EE);

    // 7) idx = argmax(logits)
    argmax_kernel<<<MTOK, 256>>>(blogits, bidx);

    // 8) d_out += moe(h, idx)
    moe_kernel<<<MTOK, 256>>>(bh, bidx, w1, b1, w2, w2b, out);
}